// round 3
// baseline (speedup 1.0000x reference)
#include <cuda_runtime.h>
#include <cuda_bf16.h>
#include <cstdint>

// ============================================================================
// Problem constants
// ============================================================================
#define DDIM 768
#define NTOT 16384
#define KAPPA 0.5f

#define KSPLIT 7
#define NPAIRS 21            // 6*7/2 upper-triangle 128x128 tiles
#define BM 128
#define BN 128
#define BK 32
#define STAGES 4
#define NCHUNK_TOT (NTOT / BK)          // 512
#define ROW_BYTES (BK * 2)              // 64
#define TILE_BYTES (BM * ROW_BYTES)     // 8192
#define STAGE_BYTES (2 * TILE_BYTES)    // 16384
#define GEMM_SMEM (STAGES * STAGE_BYTES)  // 65536

// ============================================================================
// Scratch (device globals — no allocations allowed)
// ============================================================================
__device__ __align__(1024) __nv_bfloat16 g_xt[(size_t)DDIM * NTOT];          // 25.2 MB, [d][n] bf16 K-major
__device__ __align__(16)   float g_partials[(size_t)KSPLIT * DDIM * DDIM];   // 16.5 MB
__device__ __align__(16)   float g_sumsq[256 * DDIM];                        // per n-block sum-of-squares

__constant__ unsigned char c_pairs[NPAIRS * 2] = {
    0,0, 0,1, 0,2, 0,3, 0,4, 0,5,
    1,1, 1,2, 1,3, 1,4, 1,5,
    2,2, 2,3, 2,4, 2,5,
    3,3, 3,4, 3,5,
    4,4, 4,5,
    5,5
};

// ============================================================================
// Helpers
// ============================================================================
__device__ __forceinline__ uint32_t smem_u32(const void* p) {
    uint32_t a;
    asm("{ .reg .u64 t; cvta.to.shared.u64 t, %1; cvt.u32.u64 %0, t; }" : "=r"(a) : "l"(p));
    return a;
}

// XOR swizzle: 16B chunk index XORed with bits of the row so that the 8 rows of
// any ldmatrix phase land on 8 distinct 16B slots within 128B (conflict-free).
__device__ __forceinline__ uint32_t swz(int row, int chunk) {
    return (uint32_t)((row << 6) + (((chunk ^ ((row >> 1) & 3)) & 3) << 4));
}

__device__ __forceinline__ void cp_async16(uint32_t dst, const void* src) {
    asm volatile("cp.async.cg.shared.global [%0], [%1], 16;" :: "r"(dst), "l"(src));
}
__device__ __forceinline__ void cp_commit() {
    asm volatile("cp.async.commit_group;");
}
template <int N>
__device__ __forceinline__ void cp_wait() {
    asm volatile("cp.async.wait_group %0;" :: "n"(N));
}

__device__ __forceinline__ void ldmatrix_x4(uint32_t& r0, uint32_t& r1, uint32_t& r2,
                                            uint32_t& r3, uint32_t addr) {
    asm volatile("ldmatrix.sync.aligned.m8n8.x4.shared.b16 {%0,%1,%2,%3}, [%4];"
                 : "=r"(r0), "=r"(r1), "=r"(r2), "=r"(r3) : "r"(addr));
}

__device__ __forceinline__ void mma16816(float* c, uint32_t a0, uint32_t a1, uint32_t a2,
                                         uint32_t a3, uint32_t b0, uint32_t b1) {
    asm volatile(
        "mma.sync.aligned.m16n8k16.row.col.f32.bf16.bf16.f32 "
        "{%0,%1,%2,%3}, {%4,%5,%6,%7}, {%8,%9}, {%0,%1,%2,%3};"
        : "+f"(c[0]), "+f"(c[1]), "+f"(c[2]), "+f"(c[3])
        : "r"(a0), "r"(a1), "r"(a2), "r"(a3), "r"(b0), "r"(b1));
}

// ============================================================================
// Kernel 1: transpose + fp32->bf16 convert + per-column sum-of-squares partials
// X [16384, 768] fp32 row-major -> Xt [768, 16384] bf16 row-major (K-major)
// grid: 256 n-blocks x 12 d-blocks of 64x64 tiles, 256 threads
// ============================================================================
__global__ __launch_bounds__(256) void convert_kernel(const float* __restrict__ x) {
    __shared__ uint16_t tile[64][66];
    __shared__ float red[4][64];
    int tid = threadIdx.x;
    int bn = blockIdx.x & 255;
    int bd = blockIdx.x >> 8;
    int n0 = bn * 64, d0 = bd * 64;

    int g = tid >> 6;          // 0..3
    int dl = tid & 63;
    float ss = 0.f;
#pragma unroll
    for (int i = 0; i < 16; i++) {
        int nl = i * 4 + g;
        float v = x[(size_t)(n0 + nl) * DDIM + d0 + dl];
        ss += v * v;
        __nv_bfloat16 b = __float2bfloat16(v);
        tile[nl][dl] = *reinterpret_cast<uint16_t*>(&b);
    }
    red[g][dl] = ss;
    __syncthreads();
    if (tid < 64) {
        float s = red[0][tid] + red[1][tid] + red[2][tid] + red[3][tid];
        g_sumsq[bn * DDIM + d0 + tid] = s;
    }

    // transposed write: 2 n-values packed per u32 store, coalesced along n
    int n2 = (tid & 31) * 2;
    int g2 = tid >> 5;         // 0..7
#pragma unroll
    for (int j = 0; j < 8; j++) {
        int dl2 = j * 8 + g2;
        uint32_t lo = tile[n2][dl2];
        uint32_t hi = tile[n2 + 1][dl2];
        *reinterpret_cast<uint32_t*>(&g_xt[(size_t)(d0 + dl2) * NTOT + n0 + n2]) =
            lo | (hi << 16);
    }
}

// ============================================================================
// Kernel 2: symmetric bf16 SYRK partials via mma.sync (HMMA).
// Grid = 21 upper-triangle tile pairs x 7 K-splits = 147 CTAs, 256 threads.
// Per CTA: 128x128 tile, 8 warps (2x4), warp tile 64x32, BK=32,
// 4-stage cp.async pipeline.
// B is stored [n][k] (K-contiguous) == col-major KxN for mma.row.col, so the
// B fragment uses NON-trans ldmatrix (fragment layout n=lane/4, k=2*(lane%4)).
// ============================================================================
__global__ void __launch_bounds__(256, 1) gemm_kernel() {
    extern __shared__ __align__(1024) char smem[];
    uint32_t sbase = smem_u32(smem);
    int tid = threadIdx.x;
    int lane = tid & 31;
    int wid = tid >> 5;
    int pair = blockIdx.x % NPAIRS;
    int ks = blockIdx.x / NPAIRS;
    int tm = c_pairs[pair * 2];
    int tn = c_pairs[pair * 2 + 1];
    int m0 = tm * BM;
    int n0 = tn * BN;
    int kc0 = (ks * NCHUNK_TOT) / KSPLIT;
    int kc1 = ((ks + 1) * NCHUNK_TOT) / KSPLIT;
    int nch = kc1 - kc0;
    int warp_m = wid & 1;       // 0..1
    int warp_n = wid >> 1;      // 0..3

    // per-thread load slots: 2 x (A 16B + B 16B) per stage
    int idx0 = tid;             // covers A/B rows via idx>>2, chunk idx&3
    int idx1 = tid + 256;

#define LOAD_STAGE(st, kc)                                                              \
    do {                                                                                \
        uint32_t s_ = sbase + (uint32_t)(st) * STAGE_BYTES;                             \
        int r0_ = idx0 >> 2, c0_ = idx0 & 3;                                            \
        int r1_ = idx1 >> 2, c1_ = idx1 & 3;                                            \
        const __nv_bfloat16* ga0 = &g_xt[(size_t)(m0 + r0_) * NTOT + (kc) * BK + c0_ * 8]; \
        const __nv_bfloat16* gb0 = &g_xt[(size_t)(n0 + r0_) * NTOT + (kc) * BK + c0_ * 8]; \
        const __nv_bfloat16* ga1 = &g_xt[(size_t)(m0 + r1_) * NTOT + (kc) * BK + c1_ * 8]; \
        const __nv_bfloat16* gb1 = &g_xt[(size_t)(n0 + r1_) * NTOT + (kc) * BK + c1_ * 8]; \
        cp_async16(s_ + swz(r0_, c0_), ga0);                                            \
        cp_async16(s_ + TILE_BYTES + swz(r0_, c0_), gb0);                               \
        cp_async16(s_ + swz(r1_, c1_), ga1);                                            \
        cp_async16(s_ + TILE_BYTES + swz(r1_, c1_), gb1);                               \
        cp_commit();                                                                    \
    } while (0)

    // prologue: fill STAGES-1 stages
#pragma unroll
    for (int s = 0; s < STAGES - 1; s++) {
        LOAD_STAGE(s, kc0 + s);
    }

    float acc[4][4][4];
#pragma unroll
    for (int i = 0; i < 4; i++)
#pragma unroll
        for (int j = 0; j < 4; j++)
#pragma unroll
            for (int q = 0; q < 4; q++) acc[i][j][q] = 0.f;

    // precomputed ldmatrix lane address components
    int a_row_l = lane & 15;             // row within 16
    int a_sel = lane >> 4;               // k-chunk select 0/1
    int b_row_l = (lane & 7) + ((lane >> 4) << 3);   // n row within 16
    int b_sel = (lane >> 3) & 1;         // k-chunk select 0/1

    for (int it = 0; it < nch; it++) {
        cp_wait<STAGES - 2>();
        __syncthreads();
        int st = it & (STAGES - 1);
        uint32_t sA = sbase + (uint32_t)st * STAGE_BYTES;
        uint32_t sB = sA + TILE_BYTES;

#pragma unroll
        for (int k = 0; k < 2; k++) {            // two k16 steps per BK=32
            uint32_t a[4][4];
#pragma unroll
            for (int fm = 0; fm < 4; fm++) {
                int row = warp_m * 64 + fm * 16 + a_row_l;
                int ch = k * 2 + a_sel;
                ldmatrix_x4(a[fm][0], a[fm][1], a[fm][2], a[fm][3], sA + swz(row, ch));
            }
            uint32_t b[4][2];
#pragma unroll
            for (int fp = 0; fp < 2; fp++) {     // pairs of n8 frags
                int row = warp_n * 32 + fp * 16 + b_row_l;
                int ch = k * 2 + b_sel;
                // NON-trans: B[n][k] K-contiguous is already the col-major
                // fragment layout for mma.row.col.
                ldmatrix_x4(b[fp * 2][0], b[fp * 2][1], b[fp * 2 + 1][0], b[fp * 2 + 1][1],
                            sB + swz(row, ch));
            }
#pragma unroll
            for (int fm = 0; fm < 4; fm++)
#pragma unroll
                for (int fn = 0; fn < 4; fn++)
                    mma16816(acc[fm][fn], a[fm][0], a[fm][1], a[fm][2], a[fm][3],
                             b[fn][0], b[fn][1]);
        }
        __syncthreads();
        if (it + STAGES - 1 < nch) {
            LOAD_STAGE((it + STAGES - 1) & (STAGES - 1), kc0 + it + STAGES - 1);
        } else {
            cp_commit();   // keep group count in lockstep
        }
    }

    // Epilogue: write fp32 partial tile
    float* base = &g_partials[(size_t)ks * DDIM * DDIM];
#pragma unroll
    for (int fm = 0; fm < 4; fm++) {
        int row = m0 + warp_m * 64 + fm * 16 + (lane >> 2);
#pragma unroll
        for (int fn = 0; fn < 4; fn++) {
            int col = n0 + warp_n * 32 + fn * 8 + (lane & 3) * 2;
            float* p = base + (size_t)row * DDIM + col;
            float2 v0 = make_float2(acc[fm][fn][0], acc[fm][fn][1]);
            float2 v1 = make_float2(acc[fm][fn][2], acc[fm][fn][3]);
            *reinterpret_cast<float2*>(p) = v0;
            *reinterpret_cast<float2*>(p + 8 * DDIM) = v1;
        }
    }
#undef LOAD_STAGE
}

// ============================================================================
// Kernel 3: finalize — sum ksplit partials (mirrored for lower triangle),
// scale; exact fp32 diagonal
// ============================================================================
__global__ __launch_bounds__(256) void finalize_kernel(float* __restrict__ out) {
    int idx = blockIdx.x * 256 + threadIdx.x;
    int i = idx / DDIM;
    int j = idx - i * DDIM;
    int a = i >> 7, b = j >> 7;
    size_t off = (a <= b) ? ((size_t)i * DDIM + j) : ((size_t)j * DDIM + i);
    float s = 0.f;
#pragma unroll
    for (int ks = 0; ks < KSPLIT; ks++)
        s += g_partials[(size_t)ks * DDIM * DDIM + off];
    float gme = s * (1.f / (float)NTOT);
    float val = (1.f - KAPPA) * gme - KAPPA;
    if (i == j) {
        float ssum = 0.f;
        for (int r = 0; r < 256; r++) ssum += g_sumsq[r * DDIM + i];
        val = KAPPA * (ssum * (1.f / (float)NTOT) - 1.f);
    }
    out[idx] = val;
}

// ============================================================================
// Host launch
// ============================================================================
extern "C" void kernel_launch(void* const* d_in, const int* in_sizes, int n_in,
                              void* d_out, int out_size) {
    (void)in_sizes; (void)n_in; (void)out_size;
    const float* x = (const float*)d_in[0];
    float* out = (float*)d_out;

    // 1. transpose + convert + sumsq partials
    convert_kernel<<<256 * 12, 256>>>(x);

    // 2. symmetric HMMA SYRK partials
    static bool attr_done = false;
    if (!attr_done) {
        cudaFuncSetAttribute(gemm_kernel, cudaFuncAttributeMaxDynamicSharedMemorySize,
                             GEMM_SMEM);
        attr_done = true;
    }
    gemm_kernel<<<NPAIRS * KSPLIT, 256, GEMM_SMEM>>>();

    // 3. finalize
    finalize_kernel<<<(DDIM * DDIM) / 256, 256>>>(out);
}

// round 4
// speedup vs baseline: 1.2667x; 1.2667x over previous
#include <cuda_runtime.h>
#include <cuda_bf16.h>
#include <cstdint>

// ============================================================================
// Problem constants
// ============================================================================
#define DDIM 768
#define NTOT 16384
#define KAPPA 0.5f

#define KSPLIT 7
#define NPAIRS 21            // 6*7/2 upper-triangle 128x128 tiles
#define BM 128
#define BN 128
#define BK 64
#define STAGES 4
#define NCHUNK_TOT (NTOT / BK)          // 256
#define ROW_BYTES (BK * 2)              // 128
#define TILE_BYTES (BM * ROW_BYTES)     // 16384
#define STAGE_BYTES (2 * TILE_BYTES)    // 32768
#define GEMM_SMEM (STAGES * STAGE_BYTES)  // 131072

// ============================================================================
// Scratch (device globals — no allocations allowed)
// ============================================================================
__device__ __align__(1024) __nv_bfloat16 g_xt[(size_t)DDIM * NTOT];          // 25.2 MB, [d][n] bf16 K-major
__device__ __align__(16)   float g_partials[(size_t)KSPLIT * DDIM * DDIM];   // 16.5 MB
__device__ __align__(16)   float g_sumsq[256 * DDIM];                        // per n-block sum-of-squares

__constant__ unsigned char c_pairs[NPAIRS * 2] = {
    0,0, 0,1, 0,2, 0,3, 0,4, 0,5,
    1,1, 1,2, 1,3, 1,4, 1,5,
    2,2, 2,3, 2,4, 2,5,
    3,3, 3,4, 3,5,
    4,4, 4,5,
    5,5
};

// ============================================================================
// Helpers
// ============================================================================
__device__ __forceinline__ uint32_t smem_u32(const void* p) {
    uint32_t a;
    asm("{ .reg .u64 t; cvta.to.shared.u64 t, %1; cvt.u32.u64 %0, t; }" : "=r"(a) : "l"(p));
    return a;
}

// Full-row 128B XOR swizzle: chunk (16B unit, 0..7) XOR row&7 -> conflict-free
// for both cp.async stores (8 threads cover one row) and ldmatrix (8 rows, one
// chunk: banks = ((c ^ (r&7))*4) % 32, distinct per lane).
__device__ __forceinline__ uint32_t swz(int row, int chunk) {
    return (uint32_t)((row << 7) + (((chunk ^ (row & 7)) & 7) << 4));
}

__device__ __forceinline__ void cp_async16(uint32_t dst, const void* src) {
    asm volatile("cp.async.cg.shared.global [%0], [%1], 16;" :: "r"(dst), "l"(src));
}
__device__ __forceinline__ void cp_commit() {
    asm volatile("cp.async.commit_group;");
}
template <int N>
__device__ __forceinline__ void cp_wait() {
    asm volatile("cp.async.wait_group %0;" :: "n"(N));
}

__device__ __forceinline__ void ldmatrix_x4(uint32_t& r0, uint32_t& r1, uint32_t& r2,
                                            uint32_t& r3, uint32_t addr) {
    asm volatile("ldmatrix.sync.aligned.m8n8.x4.shared.b16 {%0,%1,%2,%3}, [%4];"
                 : "=r"(r0), "=r"(r1), "=r"(r2), "=r"(r3) : "r"(addr));
}

__device__ __forceinline__ void mma16816(float* c, uint32_t a0, uint32_t a1, uint32_t a2,
                                         uint32_t a3, uint32_t b0, uint32_t b1) {
    asm volatile(
        "mma.sync.aligned.m16n8k16.row.col.f32.bf16.bf16.f32 "
        "{%0,%1,%2,%3}, {%4,%5,%6,%7}, {%8,%9}, {%0,%1,%2,%3};"
        : "+f"(c[0]), "+f"(c[1]), "+f"(c[2]), "+f"(c[3])
        : "r"(a0), "r"(a1), "r"(a2), "r"(a3), "r"(b0), "r"(b1));
}

// ============================================================================
// Kernel 1: transpose + fp32->bf16 convert + per-column sum-of-squares partials
// X [16384, 768] fp32 row-major -> Xt [768, 16384] bf16 row-major (K-major)
// grid: 256 n-blocks x 12 d-blocks of 64x64 tiles, 256 threads; float4 loads.
// ============================================================================
__global__ __launch_bounds__(256) void convert_kernel(const float* __restrict__ x) {
    __shared__ uint16_t tile[64][66];
    __shared__ float ssred[16][64];
    int tid = threadIdx.x;
    int bn = blockIdx.x & 255;
    int bd = blockIdx.x >> 8;
    int n0 = bn * 64, d0 = bd * 64;

    int c4 = (tid & 15) * 4;        // column group of 4
    int r0 = tid >> 4;              // 0..15 row phase
    float ss0 = 0.f, ss1 = 0.f, ss2 = 0.f, ss3 = 0.f;
#pragma unroll
    for (int it = 0; it < 4; it++) {
        int r = it * 16 + r0;
        float4 v = *reinterpret_cast<const float4*>(
            &x[(size_t)(n0 + r) * DDIM + d0 + c4]);
        ss0 += v.x * v.x; ss1 += v.y * v.y; ss2 += v.z * v.z; ss3 += v.w * v.w;
        __nv_bfloat162 p0 = __float22bfloat162_rn(make_float2(v.x, v.y));
        __nv_bfloat162 p1 = __float22bfloat162_rn(make_float2(v.z, v.w));
        *reinterpret_cast<uint32_t*>(&tile[r][c4])     = *reinterpret_cast<uint32_t*>(&p0);
        *reinterpret_cast<uint32_t*>(&tile[r][c4 + 2]) = *reinterpret_cast<uint32_t*>(&p1);
    }
    ssred[r0][c4 + 0] = ss0;
    ssred[r0][c4 + 1] = ss1;
    ssred[r0][c4 + 2] = ss2;
    ssred[r0][c4 + 3] = ss3;
    __syncthreads();
    if (tid < 64) {
        float s = 0.f;
#pragma unroll
        for (int g = 0; g < 16; g++) s += ssred[g][tid];
        g_sumsq[bn * DDIM + d0 + tid] = s;
    }

    // transposed write: 2 n-values packed per u32 store, coalesced along n
    int n2 = (tid & 31) * 2;
    int g2 = tid >> 5;         // 0..7
#pragma unroll
    for (int j = 0; j < 8; j++) {
        int dl2 = j * 8 + g2;
        uint32_t lo = tile[n2][dl2];
        uint32_t hi = tile[n2 + 1][dl2];
        *reinterpret_cast<uint32_t*>(&g_xt[(size_t)(d0 + dl2) * NTOT + n0 + n2]) =
            lo | (hi << 16);
    }
}

// ============================================================================
// Kernel 2: symmetric bf16 SYRK partials via mma.sync (HMMA).
// Grid = 21 upper-triangle tile pairs x 7 K-splits = 147 CTAs, 256 threads.
// 128x128 tile, 8 warps (2x4), warp tile 64x32, BK=64, 4-stage cp.async.
// B stored [n][k] K-contiguous == col-major KxN for mma.row.col -> non-trans
// ldmatrix for the B fragment.
// ============================================================================
__global__ void __launch_bounds__(256, 1) gemm_kernel() {
    extern __shared__ __align__(1024) char smem[];
    uint32_t sbase = smem_u32(smem);
    int tid = threadIdx.x;
    int lane = tid & 31;
    int wid = tid >> 5;
    int pair = blockIdx.x % NPAIRS;
    int ks = blockIdx.x / NPAIRS;
    int tm = c_pairs[pair * 2];
    int tn = c_pairs[pair * 2 + 1];
    int m0 = tm * BM;
    int n0 = tn * BN;
    int kc0 = (ks * NCHUNK_TOT) / KSPLIT;
    int kc1 = ((ks + 1) * NCHUNK_TOT) / KSPLIT;
    int nch = kc1 - kc0;
    int warp_m = wid & 1;       // 0..1
    int warp_n = wid >> 1;      // 0..3

#define LOAD_STAGE(st, kc)                                                              \
    do {                                                                                \
        uint32_t s_ = sbase + (uint32_t)(st) * STAGE_BYTES;                             \
        _Pragma("unroll")                                                               \
        for (int i_ = 0; i_ < 4; i_++) {                                                \
            int idx_ = tid + i_ * 256;                                                  \
            int r_ = idx_ >> 3, c_ = idx_ & 7;                                          \
            cp_async16(s_ + swz(r_, c_),                                                \
                       &g_xt[(size_t)(m0 + r_) * NTOT + (kc) * BK + c_ * 8]);           \
            cp_async16(s_ + TILE_BYTES + swz(r_, c_),                                   \
                       &g_xt[(size_t)(n0 + r_) * NTOT + (kc) * BK + c_ * 8]);           \
        }                                                                               \
        cp_commit();                                                                    \
    } while (0)

    // prologue: fill STAGES-1 stages
#pragma unroll
    for (int s = 0; s < STAGES - 1; s++) {
        LOAD_STAGE(s, kc0 + s);
    }

    float acc[4][4][4];
#pragma unroll
    for (int i = 0; i < 4; i++)
#pragma unroll
        for (int j = 0; j < 4; j++)
#pragma unroll
            for (int q = 0; q < 4; q++) acc[i][j][q] = 0.f;

    // ldmatrix lane address components
    int a_row_l = lane & 15;             // row within 16
    int a_sel = lane >> 4;               // k 16B-chunk select 0/1
    int b_row_l = (lane & 7) + ((lane >> 4) << 3);   // n row within 16
    int b_sel = (lane >> 3) & 1;         // k 16B-chunk select 0/1

    for (int it = 0; it < nch; it++) {
        cp_wait<STAGES - 2>();
        __syncthreads();
        int st = it & (STAGES - 1);
        uint32_t sA = sbase + (uint32_t)st * STAGE_BYTES;
        uint32_t sB = sA + TILE_BYTES;

#pragma unroll
        for (int k = 0; k < BK / 16; k++) {      // four k16 steps per BK=64
            uint32_t a[4][4];
#pragma unroll
            for (int fm = 0; fm < 4; fm++) {
                int row = warp_m * 64 + fm * 16 + a_row_l;
                int ch = k * 2 + a_sel;
                ldmatrix_x4(a[fm][0], a[fm][1], a[fm][2], a[fm][3], sA + swz(row, ch));
            }
            uint32_t b[4][2];
#pragma unroll
            for (int fp = 0; fp < 2; fp++) {     // pairs of n8 frags
                int row = warp_n * 32 + fp * 16 + b_row_l;
                int ch = k * 2 + b_sel;
                ldmatrix_x4(b[fp * 2][0], b[fp * 2][1], b[fp * 2 + 1][0], b[fp * 2 + 1][1],
                            sB + swz(row, ch));
            }
#pragma unroll
            for (int fm = 0; fm < 4; fm++)
#pragma unroll
                for (int fn = 0; fn < 4; fn++)
                    mma16816(acc[fm][fn], a[fm][0], a[fm][1], a[fm][2], a[fm][3],
                             b[fn][0], b[fn][1]);
        }
        __syncthreads();
        if (it + STAGES - 1 < nch) {
            LOAD_STAGE((it + STAGES - 1) & (STAGES - 1), kc0 + it + STAGES - 1);
        } else {
            cp_commit();   // keep group count in lockstep
        }
    }

    // Epilogue: write fp32 partial tile
    float* base = &g_partials[(size_t)ks * DDIM * DDIM];
#pragma unroll
    for (int fm = 0; fm < 4; fm++) {
        int row = m0 + warp_m * 64 + fm * 16 + (lane >> 2);
#pragma unroll
        for (int fn = 0; fn < 4; fn++) {
            int col = n0 + warp_n * 32 + fn * 8 + (lane & 3) * 2;
            float* p = base + (size_t)row * DDIM + col;
            float2 v0 = make_float2(acc[fm][fn][0], acc[fm][fn][1]);
            float2 v1 = make_float2(acc[fm][fn][2], acc[fm][fn][3]);
            *reinterpret_cast<float2*>(p) = v0;
            *reinterpret_cast<float2*>(p + 8 * DDIM) = v1;
        }
    }
#undef LOAD_STAGE
}

// ============================================================================
// Kernel 3: finalize — per-subtile: sum 7 partials coalesced, write direct +
// mirrored (via smem transpose) outputs coalesced; exact fp32 diagonal.
// Grid = 21 pairs x 16 subtiles (32x32), 256 threads.
// ============================================================================
__global__ __launch_bounds__(256) void finalize_kernel(float* __restrict__ out) {
    __shared__ float trs[32][33];
    __shared__ float dred[32][8];
    int blk = blockIdx.x;
    int pair = blk >> 4;
    int sub = blk & 15;
    int tm = c_pairs[pair * 2];
    int tn = c_pairs[pair * 2 + 1];
    int sr = sub >> 2, sc = sub & 3;
    int gi0 = tm * 128 + sr * 32;
    int gj0 = tn * 128 + sc * 32;
    int tid = threadIdx.x;
    bool diag_sub = (tm == tn) && (sr == sc);

    float vals[4];
#pragma unroll
    for (int q = 0; q < 4; q++) {
        int e = q * 256 + tid;
        int li = e >> 5, lj = e & 31;
        size_t off = (size_t)(gi0 + li) * DDIM + gj0 + lj;
        float s = 0.f;
#pragma unroll
        for (int ks = 0; ks < KSPLIT; ks++)
            s += g_partials[(size_t)ks * DDIM * DDIM + off];
        float v = (1.f - KAPPA) * (s * (1.f / (float)NTOT)) - KAPPA;
        vals[q] = v;
        trs[li][lj] = v;
    }
    if (diag_sub) {
        int d = tid >> 3, g = tid & 7;
        float ps = 0.f;
        for (int r = g; r < 256; r += 8)
            ps += g_sumsq[r * DDIM + gi0 + d];
        dred[d][g] = ps;
    }
    __syncthreads();
#pragma unroll
    for (int q = 0; q < 4; q++) {
        int e = q * 256 + tid;
        int li = e >> 5, lj = e & 31;
        float v = vals[q];
        if (diag_sub && li == lj) {
            float ssum = 0.f;
#pragma unroll
            for (int g = 0; g < 8; g++) ssum += dred[li][g];
            v = KAPPA * (ssum * (1.f / (float)NTOT) - 1.f);
        }
        out[(size_t)(gi0 + li) * DDIM + gj0 + lj] = v;
        if (tm != tn) {
            // mirrored element (gj0+li, gi0+lj) = value at (gi0+lj, gj0+li)
            out[(size_t)(gj0 + li) * DDIM + gi0 + lj] = trs[lj][li];
        }
    }
}

// ============================================================================
// Host launch
// ============================================================================
extern "C" void kernel_launch(void* const* d_in, const int* in_sizes, int n_in,
                              void* d_out, int out_size) {
    (void)in_sizes; (void)n_in; (void)out_size;
    const float* x = (const float*)d_in[0];
    float* out = (float*)d_out;

    // 1. transpose + convert + sumsq partials
    convert_kernel<<<256 * 12, 256>>>(x);

    // 2. symmetric HMMA SYRK partials
    static bool attr_done = false;
    if (!attr_done) {
        cudaFuncSetAttribute(gemm_kernel, cudaFuncAttributeMaxDynamicSharedMemorySize,
                             GEMM_SMEM);
        attr_done = true;
    }
    gemm_kernel<<<NPAIRS * KSPLIT, 256, GEMM_SMEM>>>();

    // 3. finalize
    finalize_kernel<<<NPAIRS * 16, 256>>>(out);
}